// round 4
// baseline (speedup 1.0000x reference)
#include <cuda_runtime.h>

// ContrastiveLoss: z [8192,128] fp32, labels [8192] int32 (jax downcasts int64->int32).
// loss = mean over all ordered pairs of:
//   label_eq ? d2 : relu(1 - sqrt(max(d2,0)))^2
//
// pos term: closed form per class: sum_{i,j in c} d2 = 2*n_c*S_c - 2*|M_c|^2  (O(N*D))
// neg term: only pairs with d2 < 1 contribute. Partial squared distance over the
//           first PSCR dims is a LOWER bound on d2 -> screen at O(N^2 * PSCR);
//           exact 128-dim recheck for rare candidates (sound for any input).

#define NPTS   8192
#define DIM    128
#define NC     100
#define PSCR   8           // screening dims
#define TI     1024        // i-tile per block
#define TJ     256         // j-tile per block
#define NTHR   256
#define IPT    4           // i's per thread (TI = NTHR * IPT)
#define THRESH 1.25f       // screen-out if partial d2 >= THRESH (>= 1 + fp32 slack)

// ---- scratch (no allocations allowed) ----
__device__ float  g_M[NC * DIM];   // per-class sum vector
__device__ double g_S[NC];         // per-class sum of squared norms
__device__ int    g_cnt[NC];       // per-class count
__device__ double g_neg;           // sum over unordered unequal pairs of relu(1-dist)^2
__device__ float  g_sq[NPTS];      // per-point squared norm

// ---------------- zero scratch (runs every launch; graph-replay safe) -------
__global__ void k_zero() {
    int tid = blockIdx.x * blockDim.x + threadIdx.x;
    int nt  = gridDim.x * blockDim.x;
    for (int i = tid; i < NC * DIM; i += nt) g_M[i] = 0.0f;
    for (int i = tid; i < NC; i += nt) { g_S[i] = 0.0; g_cnt[i] = 0; }
    if (tid == 0) g_neg = 0.0;
}

// ---------------- per-class aggregates + per-point sq norms -----------------
__global__ void k_agg(const float* __restrict__ z, const int* __restrict__ lab) {
    int i = blockIdx.x * blockDim.x + threadIdx.x;
    if (i >= NPTS) return;
    const float4* zr = (const float4*)(z + (size_t)i * DIM);
    int c = lab[i];
    bool ok = (c >= 0 && c < NC);
    float sq = 0.0f;
#pragma unroll
    for (int k = 0; k < DIM / 4; k++) {
        float4 v = zr[k];
        sq += v.x * v.x + v.y * v.y + v.z * v.z + v.w * v.w;
        if (ok) {
            atomicAdd(&g_M[c * DIM + 4 * k + 0], v.x);
            atomicAdd(&g_M[c * DIM + 4 * k + 1], v.y);
            atomicAdd(&g_M[c * DIM + 4 * k + 2], v.z);
            atomicAdd(&g_M[c * DIM + 4 * k + 3], v.w);
        }
    }
    g_sq[i] = sq;
    if (ok) {
        atomicAdd(&g_S[c], (double)sq);
        atomicAdd(&g_cnt[c], 1);
    }
}

// ---------------- screening pass over unordered pairs (j > i) ---------------
__global__ void __launch_bounds__(NTHR)
k_screen(const float* __restrict__ z, const int* __restrict__ lab) {
    __shared__ float4 sZ[TJ * (PSCR / 4)];
    __shared__ float  sPsq[TJ];
    __shared__ int    sLab[TJ];

    const int I0 = blockIdx.y * TI;
    const int J0 = blockIdx.x * TJ;
    if (J0 + TJ <= I0 + 1) return;               // no pair with j > i in block
    const bool needCheck = (J0 < I0 + TI);       // diagonal overlap -> per-pair j>i check

    const int tid = threadIdx.x;

    // stage j tile (first PSCR dims + partial sq norm + label)
    for (int j = tid; j < TJ; j += NTHR) {
        int jg = J0 + j;
        const float4* zr = (const float4*)(z + (size_t)jg * DIM);
        float s = 0.0f;
#pragma unroll
        for (int k = 0; k < PSCR / 4; k++) {
            float4 v = zr[k];
            sZ[j * (PSCR / 4) + k] = v;
            s += v.x * v.x + v.y * v.y + v.z * v.z + v.w * v.w;
        }
        sPsq[j] = s;
        sLab[j] = lab[jg];
    }
    __syncthreads();

    // each thread owns IPT i-rows (registers)
    float ri[IPT][PSCR];
    float psqi[IPT];
    int   labi[IPT];
#pragma unroll
    for (int t = 0; t < IPT; t++) {
        int ig = I0 + tid + t * NTHR;
        const float4* zr = (const float4*)(z + (size_t)ig * DIM);
        float s = 0.0f;
#pragma unroll
        for (int k = 0; k < PSCR / 4; k++) {
            float4 v = zr[k];
            ri[t][4 * k + 0] = v.x; ri[t][4 * k + 1] = v.y;
            ri[t][4 * k + 2] = v.z; ri[t][4 * k + 3] = v.w;
            s += v.x * v.x + v.y * v.y + v.z * v.z + v.w * v.w;
        }
        psqi[t] = s;
        labi[t] = lab[ig];
    }

    for (int j = 0; j < TJ; j++) {
        float zj[PSCR];
#pragma unroll
        for (int k = 0; k < PSCR / 4; k++) {
            float4 v = sZ[j * (PSCR / 4) + k];   // warp-uniform broadcast
            zj[4 * k + 0] = v.x; zj[4 * k + 1] = v.y;
            zj[4 * k + 2] = v.z; zj[4 * k + 3] = v.w;
        }
        const float pj = sPsq[j];
        const int   jg = J0 + j;
        const int   lj = sLab[j];
#pragma unroll
        for (int t = 0; t < IPT; t++) {
            float dot = 0.0f;
#pragma unroll
            for (int k = 0; k < PSCR; k++) dot = fmaf(ri[t][k], zj[k], dot);
            // partial squared distance = lower bound on full d2
            float pd2 = fmaf(-2.0f, dot, psqi[t] + pj);
            if (pd2 < THRESH) {                               // rare (~3.4e-4)
                int ig = I0 + tid + t * NTHR;
                if ((!needCheck || jg > ig) && lj != labi[t]) {
                    // exact 128-dim recheck, same formula as the reference
                    const float4* za = (const float4*)(z + (size_t)ig * DIM);
                    const float4* zb = (const float4*)(z + (size_t)jg * DIM);
                    float df = 0.0f;
#pragma unroll
                    for (int k = 0; k < DIM / 4; k++) {
                        float4 a = za[k], b = zb[k];
                        df += a.x * b.x + a.y * b.y + a.z * b.z + a.w * b.w;
                    }
                    float d2 = g_sq[ig] + g_sq[jg] - 2.0f * df;
                    if (d2 < 1.0f) {
                        d2 = fmaxf(d2, 0.0f);
                        float m = 1.0f - sqrtf(d2);
                        atomicAdd(&g_neg, (double)(m * m));   // unordered; x2 in finalize
                    }
                }
            }
        }
    }
}

// ---------------- finalize: analytic pos + 2*neg, divide by N^2 -------------
__global__ void k_final(float* __restrict__ out) {
    __shared__ double red[NTHR];
    int tid = threadIdx.x;
    double acc = 0.0;
    for (int idx = tid; idx < NC * DIM; idx += NTHR) {
        double m = (double)g_M[idx];
        acc -= 2.0 * m * m;
    }
    for (int c = tid; c < NC; c += NTHR)
        acc += 2.0 * (double)g_cnt[c] * g_S[c];
    red[tid] = acc;
    __syncthreads();
    for (int s = NTHR / 2; s > 0; s >>= 1) {
        if (tid < s) red[tid] += red[tid + s];
        __syncthreads();
    }
    if (tid == 0) {
        double total = red[0] + 2.0 * g_neg;
        out[0] = (float)(total / ((double)NPTS * (double)NPTS));
    }
}

extern "C" void kernel_launch(void* const* d_in, const int* in_sizes, int n_in,
                              void* d_out, int out_size) {
    const float* z   = (const float*)d_in[0];
    const int*   lab = (const int*)d_in[1];
    float*       out = (float*)d_out;

    k_zero<<<50, 256>>>();
    k_agg<<<NPTS / 256, 256>>>(z, lab);
    k_screen<<<dim3(NPTS / TJ, NPTS / TI), NTHR>>>(z, lab);
    k_final<<<1, NTHR>>>(out);
}